// round 14
// baseline (speedup 1.0000x reference)
#include <cuda_runtime.h>

static constexpr int H = 512;
static constexpr int W = 512;
static constexpr unsigned FULL = 0xFFFFFFFFu;

__device__ __forceinline__ float med3f(float a, float b, float c) {
    return fmaxf(fminf(a, b), fminf(fmaxf(a, b), c));
}

// Horizontal merge for 8 outputs of one row. lo/md/hi: [L-edge, 8 own, R-edge].
// Pair (2k+1, 2k+2) is shared by windows 2k and 2k+1.
__device__ __forceinline__ void hmerge8(const float* lo, const float* md,
                                         const float* hi, float* o) {
#pragma unroll
    for (int k = 0; k < 4; k++) {
        float pxl = fmaxf(lo[2 * k + 1], lo[2 * k + 2]);
        float pzl = fminf(hi[2 * k + 1], hi[2 * k + 2]);
        float mn  = fminf(md[2 * k + 1], md[2 * k + 2]);
        float mx  = fmaxf(md[2 * k + 1], md[2 * k + 2]);
        float X0 = fmaxf(lo[2 * k], pxl);
        float X1 = fmaxf(pxl, lo[2 * k + 3]);
        float Z0 = fminf(hi[2 * k], pzl);
        float Z1 = fminf(pzl, hi[2 * k + 3]);
        float Y0 = fmaxf(mn, fminf(mx, md[2 * k]));
        float Y1 = fmaxf(mn, fminf(mx, md[2 * k + 3]));
        o[2 * k]     = med3f(X0, Y0, Z0);
        o[2 * k + 1] = med3f(X1, Y1, Z1);
    }
}

// Merge row t into pre-sorted pair (p,q), exchange edge triples, merge, store one row.
__device__ __forceinline__ void do_row(const float* t, const float* p, const float* q,
                                        float et, float ep, float eq,
                                        bool isL, bool isR,
                                        float* __restrict__ orow, int c0) {
    float lo[10], md[10], hi[10];
#pragma unroll
    for (int i = 0; i < 8; i++) {
        float m = fmaxf(t[i], p[i]);
        lo[i + 1] = fminf(t[i], p[i]);
        hi[i + 1] = fmaxf(m, q[i]);
        md[i + 1] = fminf(m, q[i]);
    }
    float em = fmaxf(et, ep);
    float elo = fminf(et, ep), ehi = fmaxf(em, eq), emd = fminf(em, eq);
    float Ll = __shfl_up_sync(FULL, lo[8], 1);
    float Lm = __shfl_up_sync(FULL, md[8], 1);
    float Lh = __shfl_up_sync(FULL, hi[8], 1);
    float Rl = __shfl_down_sync(FULL, lo[1], 1);
    float Rm = __shfl_down_sync(FULL, md[1], 1);
    float Rh = __shfl_down_sync(FULL, hi[1], 1);
    lo[0] = isL ? elo : Ll;  md[0] = isL ? emd : Lm;  hi[0] = isL ? ehi : Lh;
    lo[9] = isR ? elo : Rl;  md[9] = isR ? emd : Rm;  hi[9] = isR ? ehi : Rh;
    float o[8];
    hmerge8(lo, md, hi, o);
    *(float4*)(orow + c0)     = make_float4(o[0], o[1], o[2], o[3]);
    *(float4*)(orow + c0 + 4) = make_float4(o[4], o[5], o[6], o[7]);
}

__global__ __launch_bounds__(128, 4)
void median3x3_kernel(const float* __restrict__ in, float* __restrict__ out, int nimg) {
    const int gwarp = (blockIdx.x * blockDim.x + threadIdx.x) >> 5;
    const int lane = threadIdx.x & 31;

    // Warp strip: 16 output rows x 256 cols = 4 vertical quads, rolling pipeline.
    const int img = gwarp >> 6;                      // 64 strips per image
    if (img >= nimg) return;
    const int rem = gwarp & 63;
    const int ybase = (rem >> 1) << 4;               // 0,16,...,496
    const int c0 = ((rem & 1) << 8) + (lane << 3);   // 8 columns per lane

    const float* __restrict__ base = in + (size_t)img * (H * W);
    float* __restrict__ obase = out + (size_t)img * (H * W);

    const bool isL = (lane == 0);
    const bool isR = (lane == 31);
    const int ecol = isL ? (c0 - 1) : (c0 + 8);
    const bool ev = (isL | isR) && ((unsigned)ecol < (unsigned)W);
    const float4 zero4 = make_float4(0.f, 0.f, 0.f, 0.f);

    // Current quad's 6 input rows + edge column, register-resident.
    float cur[6][8];
    float ecur[6];
    {
        const bool topOK = (ybase > 0);
#pragma unroll
        for (int r = 0; r < 6; r++) {
            const int gy = ybase - 1 + r;            // ybase-1 .. ybase+4 (all < H)
            const bool ok = (r > 0) || topOK;
            float4 a = ok ? *(const float4*)(base + gy * W + c0)     : zero4;
            float4 b = ok ? *(const float4*)(base + gy * W + c0 + 4) : zero4;
            cur[r][0] = a.x; cur[r][1] = a.y; cur[r][2] = a.z; cur[r][3] = a.w;
            cur[r][4] = b.x; cur[r][5] = b.y; cur[r][6] = b.z; cur[r][7] = b.w;
            ecur[r] = (ev && ok) ? base[gy * W + ecol] : 0.f;
        }
    }

#pragma unroll 1
    for (int iq = 0; iq < 4; iq++) {
        const int y0 = ybase + 4 * iq;

        // ---- Prefetch next quad's 4 NEW rows (y0+5 .. y0+8) BEFORE compute ----
        float4 na[4], nb[4];
        float ne[4];
        if (iq < 3) {
#pragma unroll
            for (int r = 0; r < 4; r++) {
                const int gy = y0 + 5 + r;
                const bool ok = (gy < H);
                na[r] = ok ? *(const float4*)(base + gy * W + c0)     : zero4;
                nb[r] = ok ? *(const float4*)(base + gy * W + c0 + 4) : zero4;
                ne[r] = (ev && ok) ? base[gy * W + ecol] : 0.f;
            }
        }

        // ---- Compute current quad (R5 network) ----
        float pv[8], qv[8];
#pragma unroll
        for (int i = 0; i < 8; i++) {
            pv[i] = fminf(cur[1][i], cur[2][i]);
            qv[i] = fmaxf(cur[1][i], cur[2][i]);
        }
        {
            const float epA = fminf(ecur[1], ecur[2]), eqA = fmaxf(ecur[1], ecur[2]);
            do_row(cur[0], pv, qv, ecur[0], epA, eqA, isL, isR, obase + (y0    ) * W, c0);
            do_row(cur[3], pv, qv, ecur[3], epA, eqA, isL, isR, obase + (y0 + 1) * W, c0);
        }
#pragma unroll
        for (int i = 0; i < 8; i++) {
            float mn = fminf(cur[3][i], cur[4][i]);
            float mx = fmaxf(cur[3][i], cur[4][i]);
            pv[i] = mn;
            qv[i] = mx;
        }
        {
            const float epB = fminf(ecur[3], ecur[4]), eqB = fmaxf(ecur[3], ecur[4]);
            do_row(cur[2], pv, qv, ecur[2], epB, eqB, isL, isR, obase + (y0 + 2) * W, c0);
            do_row(cur[5], pv, qv, ecur[5], epB, eqB, isL, isR, obase + (y0 + 3) * W, c0);
        }

        // ---- Rotate: carry rows i4,i5 -> next i0,i1; install prefetched rows ----
        if (iq < 3) {
#pragma unroll
            for (int i = 0; i < 8; i++) {
                cur[0][i] = cur[4][i];
                cur[1][i] = cur[5][i];
            }
            ecur[0] = ecur[4];
            ecur[1] = ecur[5];
#pragma unroll
            for (int r = 0; r < 4; r++) {
                cur[2 + r][0] = na[r].x; cur[2 + r][1] = na[r].y;
                cur[2 + r][2] = na[r].z; cur[2 + r][3] = na[r].w;
                cur[2 + r][4] = nb[r].x; cur[2 + r][5] = nb[r].y;
                cur[2 + r][6] = nb[r].z; cur[2 + r][7] = nb[r].w;
                ecur[2 + r] = ne[r];
            }
        }
    }
}

extern "C" void kernel_launch(void* const* d_in, const int* in_sizes, int n_in,
                              void* d_out, int out_size) {
    const float* x = (const float*)d_in[0];
    float* y = (float*)d_out;
    const int nimg = in_sizes[0] / (H * W);            // B*C images
    const int warps = nimg * (H / 16) * 2;             // 32 y-groups x 2 halves
    const int threads = warps * 32;
    const int block = 128;
    const int grid = (threads + block - 1) / block;
    median3x3_kernel<<<grid, block>>>(x, y, nimg);
}

// round 15
// speedup vs baseline: 1.4324x; 1.4324x over previous
#include <cuda_runtime.h>

static constexpr int H = 512;
static constexpr int W = 512;
static constexpr unsigned FULL = 0xFFFFFFFFu;

__device__ __forceinline__ float med3f(float a, float b, float c) {
    return fmaxf(fminf(a, b), fminf(fmaxf(a, b), c));
}

// Streaming store (evict-first): output is write-once, never re-read.
__device__ __forceinline__ void stcs4(float* p, float a, float b, float c, float d) {
    asm volatile("st.global.cs.v4.f32 [%0], {%1, %2, %3, %4};"
                 :: "l"(p), "f"(a), "f"(b), "f"(c), "f"(d) : "memory");
}

// Horizontal merge for 8 outputs of one row.
// lo/md/hi: [L-edge, 8 own columns, R-edge], each vertically sorted.
// Pair (2k+1, 2k+2) is shared by windows 2k and 2k+1.
__device__ __forceinline__ void hmerge8(const float* lo, const float* md,
                                         const float* hi, float* o) {
#pragma unroll
    for (int k = 0; k < 4; k++) {
        float pxl = fmaxf(lo[2 * k + 1], lo[2 * k + 2]);
        float pzl = fminf(hi[2 * k + 1], hi[2 * k + 2]);
        float mn  = fminf(md[2 * k + 1], md[2 * k + 2]);
        float mx  = fmaxf(md[2 * k + 1], md[2 * k + 2]);
        float X0 = fmaxf(lo[2 * k], pxl);
        float X1 = fmaxf(pxl, lo[2 * k + 3]);
        float Z0 = fminf(hi[2 * k], pzl);
        float Z1 = fminf(pzl, hi[2 * k + 3]);
        float Y0 = fmaxf(mn, fminf(mx, md[2 * k]));
        float Y1 = fmaxf(mn, fminf(mx, md[2 * k + 3]));
        o[2 * k]     = med3f(X0, Y0, Z0);
        o[2 * k + 1] = med3f(X1, Y1, Z1);
    }
}

// Merge row t into pre-sorted pair (p,q), exchange edge triples, merge, store one row.
__device__ __forceinline__ void do_row(const float* t, const float* p, const float* q,
                                        float et, float ep, float eq,
                                        bool isL, bool isR,
                                        float* __restrict__ orow, int c0) {
    float lo[10], md[10], hi[10];
#pragma unroll
    for (int i = 0; i < 8; i++) {
        float m = fmaxf(t[i], p[i]);
        lo[i + 1] = fminf(t[i], p[i]);
        hi[i + 1] = fmaxf(m, q[i]);
        md[i + 1] = fminf(m, q[i]);
    }
    float em = fmaxf(et, ep);
    float elo = fminf(et, ep), ehi = fmaxf(em, eq), emd = fminf(em, eq);
    float Ll = __shfl_up_sync(FULL, lo[8], 1);
    float Lm = __shfl_up_sync(FULL, md[8], 1);
    float Lh = __shfl_up_sync(FULL, hi[8], 1);
    float Rl = __shfl_down_sync(FULL, lo[1], 1);
    float Rm = __shfl_down_sync(FULL, md[1], 1);
    float Rh = __shfl_down_sync(FULL, hi[1], 1);
    lo[0] = isL ? elo : Ll;  md[0] = isL ? emd : Lm;  hi[0] = isL ? ehi : Lh;
    lo[9] = isR ? elo : Rl;  md[9] = isR ? emd : Rm;  hi[9] = isR ? ehi : Rh;
    float o[8];
    hmerge8(lo, md, hi, o);
    stcs4(orow + c0,     o[0], o[1], o[2], o[3]);
    stcs4(orow + c0 + 4, o[4], o[5], o[6], o[7]);
}

__global__ __launch_bounds__(128, 6)
void median3x3_kernel(const float* __restrict__ in, float* __restrict__ out, int nimg) {
    const int gwarp = (blockIdx.x * blockDim.x + threadIdx.x) >> 5;
    const int lane = threadIdx.x & 31;

    // Per image: 128 row-quads (4 output rows each) x 2 warp-column-groups (256 cols each).
    const int img = gwarp >> 8;
    if (img >= nimg) return;
    const int rem = gwarp & 255;
    const int y0 = (rem >> 1) << 2;                  // 0,4,...,508
    const int c0 = ((rem & 1) << 8) + (lane << 3);   // 8 columns per lane

    const float* __restrict__ base = in + (size_t)img * (H * W);
    float* __restrict__ obase = out + (size_t)img * (H * W);

    // ---- Load 6 input rows (y0-1 .. y0+4) x 8 cols: 12 x LDG.128, max MLP ----
    const float4 zero4 = make_float4(0.f, 0.f, 0.f, 0.f);
    const bool topOK = (y0 > 0);
    const bool botOK = (y0 + 4 < H);
    float4 i0a = topOK ? *(const float4*)(base + (y0 - 1) * W + c0)     : zero4;
    float4 i0b = topOK ? *(const float4*)(base + (y0 - 1) * W + c0 + 4) : zero4;
    float4 i1a =         *(const float4*)(base + (y0    ) * W + c0);
    float4 i1b =         *(const float4*)(base + (y0    ) * W + c0 + 4);
    float4 i2a =         *(const float4*)(base + (y0 + 1) * W + c0);
    float4 i2b =         *(const float4*)(base + (y0 + 1) * W + c0 + 4);
    float4 i3a =         *(const float4*)(base + (y0 + 2) * W + c0);
    float4 i3b =         *(const float4*)(base + (y0 + 2) * W + c0 + 4);
    float4 i4a =         *(const float4*)(base + (y0 + 3) * W + c0);
    float4 i4b =         *(const float4*)(base + (y0 + 3) * W + c0 + 4);
    float4 i5a = botOK ? *(const float4*)(base + (y0 + 4) * W + c0)     : zero4;
    float4 i5b = botOK ? *(const float4*)(base + (y0 + 4) * W + c0 + 4) : zero4;

    // Warp-edge boundary column (6 rows), lanes 0/31 only.
    const bool isL = (lane == 0);
    const bool isR = (lane == 31);
    const int ecol = isL ? (c0 - 1) : (c0 + 8);
    const bool ev = (isL | isR) && ((unsigned)ecol < (unsigned)W);
    float e0 = (ev && topOK) ? base[(y0 - 1) * W + ecol] : 0.f;
    float e1 = ev            ? base[(y0    ) * W + ecol] : 0.f;
    float e2 = ev            ? base[(y0 + 1) * W + ecol] : 0.f;
    float e3 = ev            ? base[(y0 + 2) * W + ecol] : 0.f;
    float e4 = ev            ? base[(y0 + 3) * W + ecol] : 0.f;
    float e5 = (ev && botOK) ? base[(y0 + 4) * W + ecol] : 0.f;

    float r2[8] = {i2a.x, i2a.y, i2a.z, i2a.w, i2b.x, i2b.y, i2b.z, i2b.w};
    float r3[8] = {i3a.x, i3a.y, i3a.z, i3a.w, i3b.x, i3b.y, i3b.z, i3b.w};

    // ---- Pair A = sort(i1, i2); i1 dies here ----
    float p[8], q[8];
    {
        float r1[8] = {i1a.x, i1a.y, i1a.z, i1a.w, i1b.x, i1b.y, i1b.z, i1b.w};
#pragma unroll
        for (int i = 0; i < 8; i++) {
            p[i] = fminf(r1[i], r2[i]);
            q[i] = fmaxf(r1[i], r2[i]);
        }
    }
    {
        const float epA = fminf(e1, e2), eqA = fmaxf(e1, e2);
        // Rows o0 = (i0, i1, i2), o1 = (i1, i2, i3) via shared pair A.
        float t0[8] = {i0a.x, i0a.y, i0a.z, i0a.w, i0b.x, i0b.y, i0b.z, i0b.w};
        do_row(t0, p, q, e0, epA, eqA, isL, isR, obase + (y0    ) * W, c0);
        do_row(r3, p, q, e3, epA, eqA, isL, isR, obase + (y0 + 1) * W, c0);
    }

    // ---- Pair B = sort(i3, i4); reuse p,q storage ----
    {
        float r4[8] = {i4a.x, i4a.y, i4a.z, i4a.w, i4b.x, i4b.y, i4b.z, i4b.w};
#pragma unroll
        for (int i = 0; i < 8; i++) {
            float mn = fminf(r3[i], r4[i]);
            float mx = fmaxf(r3[i], r4[i]);
            p[i] = mn;
            q[i] = mx;
        }
    }
    {
        const float epB = fminf(e3, e4), eqB = fmaxf(e3, e4);
        // Rows o2 = (i2, i3, i4), o3 = (i3, i4, i5) via shared pair B.
        do_row(r2, p, q, e2, epB, eqB, isL, isR, obase + (y0 + 2) * W, c0);
        float t5[8] = {i5a.x, i5a.y, i5a.z, i5a.w, i5b.x, i5b.y, i5b.z, i5b.w};
        do_row(t5, p, q, e5, epB, eqB, isL, isR, obase + (y0 + 3) * W, c0);
    }
}

extern "C" void kernel_launch(void* const* d_in, const int* in_sizes, int n_in,
                              void* d_out, int out_size) {
    const float* x = (const float*)d_in[0];
    float* y = (float*)d_out;
    const int nimg = in_sizes[0] / (H * W);                  // B*C images
    const int warps = nimg * (H / 4) * (W / 256);            // 128 row-quads x 2 groups
    const int threads = warps * 32;
    const int block = 128;
    const int grid = (threads + block - 1) / block;
    median3x3_kernel<<<grid, block>>>(x, y, nimg);
}